// round 3
// baseline (speedup 1.0000x reference)
#include <cuda_runtime.h>
#include <cuda_fp16.h>
#include <cstdint>

#define H 768
#define BATCHN 128
#define TM 128
#define TN 128
#define TK 32
#define NKT (H / TK)      // 24
#define NJT (H / TN)      // 6
#define NTHREADS 256

// SMEM: 4 tiles (op_hi, op_lo, in_hi, in_lo), each 128 rows x 80 bytes (32 halves + pad)
#define ROWB 80
#define TILE_B (128 * ROWB)            // 10240
#define OFF_OPHI 0
#define OFF_OPLO (TILE_B)
#define OFF_INHI (2 * TILE_B)
#define OFF_INLO (3 * TILE_B)
#define STAGE_B (4 * TILE_B)           // 40960
#define OFF_SP (2 * STAGE_B)           // partials: 2*128 floats
#define SMEM_TOTAL (OFF_SP + 2 * 128 * 4)

__device__ float g_logits[BATCHN * H];

__device__ __forceinline__ uint32_t smem_u32(const void* p) {
    uint32_t a;
    asm("{ .reg .u64 t; cvta.to.shared.u64 t, %1; cvt.u32.u64 %0, t; }" : "=r"(a) : "l"(p));
    return a;
}
__device__ __forceinline__ void ldsm4(uint32_t* r, uint32_t addr) {
    asm volatile("ldmatrix.sync.aligned.m8n8.x4.shared.b16 {%0,%1,%2,%3}, [%4];"
                 : "=r"(r[0]), "=r"(r[1]), "=r"(r[2]), "=r"(r[3]) : "r"(addr));
}
__device__ __forceinline__ void mma16816(float* d, const uint32_t* a, const uint32_t* b) {
    asm volatile(
        "mma.sync.aligned.m16n8k16.row.col.f32.f16.f16.f32 "
        "{%0,%1,%2,%3}, {%4,%5,%6,%7}, {%8,%9}, {%0,%1,%2,%3};"
        : "+f"(d[0]), "+f"(d[1]), "+f"(d[2]), "+f"(d[3])
        : "r"(a[0]), "r"(a[1]), "r"(a[2]), "r"(a[3]), "r"(b[0]), "r"(b[1]));
}
__device__ __forceinline__ uint32_t pack2(__half a, __half b) {
    __half2 h = __halves2half2(a, b);
    return *reinterpret_cast<uint32_t*>(&h);
}
// convert float4 -> hi/lo fp16 quads, store at (row, c4) in both tiles
__device__ __forceinline__ void cvt_store(char* base_hi, char* base_lo, int row, int c4, float4 v) {
    __half hx = __float2half_rn(v.x), hy = __float2half_rn(v.y);
    __half hz = __float2half_rn(v.z), hw = __float2half_rn(v.w);
    __half lx = __float2half_rn(v.x - __half2float(hx));
    __half ly = __float2half_rn(v.y - __half2float(hy));
    __half lz = __float2half_rn(v.z - __half2float(hz));
    __half lw = __float2half_rn(v.w - __half2float(hw));
    int off = row * ROWB + c4 * 8;
    *reinterpret_cast<uint2*>(base_hi + off) = make_uint2(pack2(hx, hy), pack2(hz, hw));
    *reinterpret_cast<uint2*>(base_lo + off) = make_uint2(pack2(lx, ly), pack2(lz, lw));
}

// grid: (H/TM = 6, BATCHN = 128)
__global__ void __launch_bounds__(NTHREADS)
Measurement_68307159875839_gemm(const float* __restrict__ inp, const float* __restrict__ op) {
    extern __shared__ __align__(16) char smem[];
    const uint32_t smem_base = smem_u32(smem);
    const int tid = threadIdx.x;
    const int lane = tid & 31;
    const int w = tid >> 5;
    const int mw = w & 3;          // 4 M-warps: i
    const int nw = w >> 2;         // 2 N-warps: j
    const int i0 = blockIdx.x * TM;
    const int b = blockIdx.y;
    const float* inb = inp + (size_t)b * H * H;

    // ldmatrix per-lane byte offsets within a tile (add mt*16*ROWB / u*16*ROWB, k16*32)
    const uint32_t a_off = (uint32_t)((mw * 32 + (lane & 15)) * ROWB + (lane >> 4) * 16);
    const uint32_t b_off = (uint32_t)((nw * 64 + (lane & 7) + ((lane & 16) >> 1)) * ROWB +
                                      ((lane >> 3) & 1) * 16);

    float part_acc[2][2] = {{0.f, 0.f}, {0.f, 0.f}};

    for (int jt = 0; jt < NJT; ++jt) {
        const int j0 = jt * TN;
        float acc[2][8][4];
#pragma unroll
        for (int mt = 0; mt < 2; mt++)
#pragma unroll
            for (int nt = 0; nt < 8; nt++)
#pragma unroll
                for (int e = 0; e < 4; e++) acc[mt][nt][e] = 0.f;

        // ---- preload k-tile 0 into stage 0 ----
        {
            float4 vop[4], vin[4];
#pragma unroll
            for (int r = 0; r < 4; r++) {
                int idx = r * NTHREADS + tid, row = idx >> 3, c4 = idx & 7;
                vop[r] = *reinterpret_cast<const float4*>(op + (size_t)(i0 + row) * H + c4 * 4);
                vin[r] = *reinterpret_cast<const float4*>(inb + (size_t)(j0 + row) * H + c4 * 4);
            }
#pragma unroll
            for (int r = 0; r < 4; r++) {
                int idx = r * NTHREADS + tid, row = idx >> 3, c4 = idx & 7;
                cvt_store(smem + OFF_OPHI, smem + OFF_OPLO, row, c4, vop[r]);
                cvt_store(smem + OFF_INHI, smem + OFF_INLO, row, c4, vin[r]);
            }
        }
        __syncthreads();

        for (int kt = 0; kt < NKT; ++kt) {
            // prefetch next k-tile
            float4 vop[4], vin[4];
            if (kt + 1 < NKT) {
                const int kb = (kt + 1) * TK;
#pragma unroll
                for (int r = 0; r < 4; r++) {
                    int idx = r * NTHREADS + tid, row = idx >> 3, c4 = idx & 7;
                    vop[r] = *reinterpret_cast<const float4*>(op + (size_t)(i0 + row) * H + kb + c4 * 4);
                    vin[r] = *reinterpret_cast<const float4*>(inb + (size_t)(j0 + row) * H + kb + c4 * 4);
                }
            }
            const uint32_t sb = smem_base + (uint32_t)((kt & 1) * STAGE_B);
#pragma unroll
            for (int k16 = 0; k16 < 2; k16++) {
                const uint32_t kofs = (uint32_t)(k16 * 32);
                uint32_t ah[2][4], al[2][4], bh[8][2], bl[8][2];
#pragma unroll
                for (int mt = 0; mt < 2; mt++) {
                    ldsm4(ah[mt], sb + OFF_OPHI + a_off + mt * 16 * ROWB + kofs);
                    ldsm4(al[mt], sb + OFF_OPLO + a_off + mt * 16 * ROWB + kofs);
                }
#pragma unroll
                for (int up = 0; up < 4; up++) {
                    uint32_t r4[4];
                    ldsm4(r4, sb + OFF_INHI + b_off + up * 16 * ROWB + kofs);
                    bh[2 * up][0] = r4[0]; bh[2 * up][1] = r4[1];
                    bh[2 * up + 1][0] = r4[2]; bh[2 * up + 1][1] = r4[3];
                    ldsm4(r4, sb + OFF_INLO + b_off + up * 16 * ROWB + kofs);
                    bl[2 * up][0] = r4[0]; bl[2 * up][1] = r4[1];
                    bl[2 * up + 1][0] = r4[2]; bl[2 * up + 1][1] = r4[3];
                }
                // hi*hi, then hi*lo, then lo*hi (long RAW distance per accumulator)
#pragma unroll
                for (int mt = 0; mt < 2; mt++)
#pragma unroll
                    for (int nt = 0; nt < 8; nt++) mma16816(acc[mt][nt], ah[mt], bh[nt]);
#pragma unroll
                for (int mt = 0; mt < 2; mt++)
#pragma unroll
                    for (int nt = 0; nt < 8; nt++) mma16816(acc[mt][nt], ah[mt], bl[nt]);
#pragma unroll
                for (int mt = 0; mt < 2; mt++)
#pragma unroll
                    for (int nt = 0; nt < 8; nt++) mma16816(acc[mt][nt], al[mt], bh[nt]);
            }
            if (kt + 1 < NKT) {
                char* st = smem + ((kt + 1) & 1) * STAGE_B;
#pragma unroll
                for (int r = 0; r < 4; r++) {
                    int idx = r * NTHREADS + tid, row = idx >> 3, c4 = idx & 7;
                    cvt_store(st + OFF_OPHI, st + OFF_OPLO, row, c4, vop[r]);
                    cvt_store(st + OFF_INHI, st + OFF_INLO, row, c4, vin[r]);
                }
            }
            __syncthreads();
        }

        // ---- epilogue: part_acc[mt][ir] += sum_j D[i,j] * op[i, j] ----
#pragma unroll
        for (int mt = 0; mt < 2; mt++)
#pragma unroll
            for (int ir = 0; ir < 2; ir++) {
                const int i_g = i0 + mw * 32 + mt * 16 + (lane >> 2) + ir * 8;
                const float* oprow = op + (size_t)i_g * H + j0 + nw * 64 + (lane & 3) * 2;
                float s = 0.f;
#pragma unroll
                for (int nt = 0; nt < 8; nt++) {
                    float2 w2 = *reinterpret_cast<const float2*>(oprow + nt * 8);
                    s += acc[mt][nt][ir * 2 + 0] * w2.x + acc[mt][nt][ir * 2 + 1] * w2.y;
                }
                part_acc[mt][ir] += s;
            }
    }

    // reduce the 4 lanes (lane&3) that share the same i, then combine 2 N-warps via smem
#pragma unroll
    for (int mt = 0; mt < 2; mt++)
#pragma unroll
        for (int ir = 0; ir < 2; ir++) {
            float v = part_acc[mt][ir];
            v += __shfl_xor_sync(0xffffffffu, v, 1);
            v += __shfl_xor_sync(0xffffffffu, v, 2);
            part_acc[mt][ir] = v;
        }
    float* sp = reinterpret_cast<float*>(smem + OFF_SP);
    if ((lane & 3) == 0) {
#pragma unroll
        for (int mt = 0; mt < 2; mt++)
#pragma unroll
            for (int ir = 0; ir < 2; ir++) {
                int i_loc = mw * 32 + mt * 16 + (lane >> 2) + ir * 8;
                sp[nw * 128 + i_loc] = part_acc[mt][ir];
            }
    }
    __syncthreads();
    for (int i = tid; i < TM; i += NTHREADS)
        g_logits[b * H + i0 + i] = sp[i] + sp[128 + i];
}

// one block per batch row: softmax over 768 logits
__global__ void Measurement_68307159875839_softmax(float* __restrict__ out) {
    __shared__ float red[NTHREADS / 32];
    const int b = blockIdx.x, tid = threadIdx.x;
    const float* row = g_logits + b * H;
    float m = -1e30f;
    for (int i = tid; i < H; i += NTHREADS) m = fmaxf(m, row[i]);
#pragma unroll
    for (int o = 16; o > 0; o >>= 1) m = fmaxf(m, __shfl_xor_sync(0xffffffffu, m, o));
    if ((tid & 31) == 0) red[tid >> 5] = m;
    __syncthreads();
    m = red[0];
#pragma unroll
    for (int wv = 1; wv < NTHREADS / 32; wv++) m = fmaxf(m, red[wv]);
    __syncthreads();
    float s = 0.0f;
    for (int i = tid; i < H; i += NTHREADS) s += __expf(row[i] - m);
#pragma unroll
    for (int o = 16; o > 0; o >>= 1) s += __shfl_xor_sync(0xffffffffu, s, o);
    if ((tid & 31) == 0) red[tid >> 5] = s;
    __syncthreads();
    s = 0.0f;
#pragma unroll
    for (int wv = 0; wv < NTHREADS / 32; wv++) s += red[wv];
    const float inv = 1.0f / s;
    for (int i = tid; i < H; i += NTHREADS) out[b * H + i] = __expf(row[i] - m) * inv;
}

extern "C" void kernel_launch(void* const* d_in, const int* in_sizes, int n_in,
                              void* d_out, int out_size) {
    const float* inputs = (const float*)d_in[0];   // [128, 768, 768] fp32
    const float* op     = (const float*)d_in[1];   // [768, 768] fp32
    float* out = (float*)d_out;                    // [128, 768] fp32
    static int configured = 0;
    if (!configured) {
        cudaFuncSetAttribute(Measurement_68307159875839_gemm,
                             cudaFuncAttributeMaxDynamicSharedMemorySize, SMEM_TOTAL);
        configured = 1;
    }
    Measurement_68307159875839_gemm<<<dim3(H / TM, BATCHN), NTHREADS, SMEM_TOTAL>>>(inputs, op);
    Measurement_68307159875839_softmax<<<BATCHN, NTHREADS>>>(out);
}

// round 4
// speedup vs baseline: 1.0047x; 1.0047x over previous
#include <cuda_runtime.h>
#include <cuda_fp16.h>
#include <cstdint>

#define H 768
#define BATCHN 128
#define TM 128
#define TN 128
#define TK 32
#define NKT (H / TK)      // 24
#define NJT (H / TN)      // 6
#define NTHREADS 256

// SMEM: per stage 4 tiles (op_hi, op_lo, in_hi, in_lo), 128 rows x 80B pitch (64B data + pad)
#define ROWB 80
#define TILE_B (128 * ROWB)            // 10240
#define OFF_OPHI 0
#define OFF_OPLO (TILE_B)
#define OFF_INHI (2 * TILE_B)
#define OFF_INLO (3 * TILE_B)
#define STAGE_B (4 * TILE_B)           // 40960
#define OFF_SP (2 * STAGE_B)           // partials: 2*128 floats
#define SMEM_TOTAL (OFF_SP + 2 * 128 * 4)   // 82944

__device__ float g_logits[BATCHN * H];
__device__ __half g_in_hi[(size_t)BATCHN * H * H];
__device__ __half g_in_lo[(size_t)BATCHN * H * H];
__device__ __half g_op_hi[H * H];
__device__ __half g_op_lo[H * H];

// ---------------- helpers ----------------
__device__ __forceinline__ uint32_t smem_u32(const void* p) {
    uint32_t a;
    asm("{ .reg .u64 t; cvta.to.shared.u64 t, %1; cvt.u32.u64 %0, t; }" : "=r"(a) : "l"(p));
    return a;
}
__device__ __forceinline__ void ldsm4(uint32_t* r, uint32_t addr) {
    asm volatile("ldmatrix.sync.aligned.m8n8.x4.shared.b16 {%0,%1,%2,%3}, [%4];"
                 : "=r"(r[0]), "=r"(r[1]), "=r"(r[2]), "=r"(r[3]) : "r"(addr));
}
__device__ __forceinline__ void mma16816(float* d, const uint32_t* a, const uint32_t* b) {
    asm volatile(
        "mma.sync.aligned.m16n8k16.row.col.f32.f16.f16.f32 "
        "{%0,%1,%2,%3}, {%4,%5,%6,%7}, {%8,%9}, {%0,%1,%2,%3};"
        : "+f"(d[0]), "+f"(d[1]), "+f"(d[2]), "+f"(d[3])
        : "r"(a[0]), "r"(a[1]), "r"(a[2]), "r"(a[3]), "r"(b[0]), "r"(b[1]));
}
__device__ __forceinline__ void cp16(uint32_t dst, const void* src) {
    asm volatile("cp.async.cg.shared.global [%0], [%1], 16;" :: "r"(dst), "l"(src));
}
__device__ __forceinline__ void cp_commit() {
    asm volatile("cp.async.commit_group;" ::: "memory");
}
__device__ __forceinline__ void cp_wait1() {
    asm volatile("cp.async.wait_group 1;" ::: "memory");
}
__device__ __forceinline__ void cp_wait0() {
    asm volatile("cp.async.wait_group 0;" ::: "memory");
}
__device__ __forceinline__ uint32_t pack2(__half a, __half b) {
    __half2 h = __halves2half2(a, b);
    return *reinterpret_cast<uint32_t*>(&h);
}

// ---------------- pre-pass: fp32 -> fp16 hi/lo ----------------
__global__ void Measurement_68307159875839_cvt(const float* __restrict__ src,
                                               __half* __restrict__ dst_hi,
                                               __half* __restrict__ dst_lo, int n4) {
    int idx = blockIdx.x * blockDim.x + threadIdx.x;
    if (idx >= n4) return;
    float4 v = reinterpret_cast<const float4*>(src)[idx];
    __half hx = __float2half_rn(v.x), hy = __float2half_rn(v.y);
    __half hz = __float2half_rn(v.z), hw = __float2half_rn(v.w);
    __half lx = __float2half_rn(v.x - __half2float(hx));
    __half ly = __float2half_rn(v.y - __half2float(hy));
    __half lz = __float2half_rn(v.z - __half2float(hz));
    __half lw = __float2half_rn(v.w - __half2float(hw));
    reinterpret_cast<uint2*>(dst_hi)[idx] = make_uint2(pack2(hx, hy), pack2(hz, hw));
    reinterpret_cast<uint2*>(dst_lo)[idx] = make_uint2(pack2(lx, ly), pack2(lz, lw));
}

// ---------------- GEMM + fused diag ----------------
// grid: (H/TM = 6, BATCHN = 128); 6 CTAs of a batch are adjacent -> inputs L2 reuse.
__device__ __forceinline__ void fill_stage(uint32_t smem_base, int s, int i0, int j0,
                                           int k0, size_t in_off, int tid) {
#pragma unroll
    for (int r = 0; r < 8; r++) {
        int q = r * NTHREADS + tid;          // 2048 chunks: 4 tiles x 128 rows x 4 x 16B
        int tile = q >> 9;
        int rem = q & 511;
        int row = rem >> 2;
        int c = rem & 3;
        uint32_t dst = smem_base + (uint32_t)(s * STAGE_B + tile * TILE_B + row * ROWB + c * 16);
        const __half* src;
        if (tile == 0)      src = g_op_hi + (size_t)(i0 + row) * H + k0 + c * 8;
        else if (tile == 1) src = g_op_lo + (size_t)(i0 + row) * H + k0 + c * 8;
        else if (tile == 2) src = g_in_hi + in_off + (size_t)(j0 + row) * H + k0 + c * 8;
        else                src = g_in_lo + in_off + (size_t)(j0 + row) * H + k0 + c * 8;
        cp16(dst, src);
    }
}

__global__ void __launch_bounds__(NTHREADS)
Measurement_68307159875839_gemm(const float* __restrict__ op) {
    extern __shared__ __align__(16) char smem[];
    const uint32_t smem_base = smem_u32(smem);
    const int tid = threadIdx.x;
    const int lane = tid & 31;
    const int w = tid >> 5;
    const int mw = w & 3;          // 4 M-warps (i)
    const int nw = w >> 2;         // 2 N-warps (j)
    const int i0 = blockIdx.x * TM;
    const int b = blockIdx.y;
    const size_t in_off = (size_t)b * H * H;

    const uint32_t a_off = (uint32_t)((mw * 32 + (lane & 15)) * ROWB + (lane >> 4) * 16);
    const uint32_t b_off = (uint32_t)((nw * 64 + (lane & 7) + ((lane & 16) >> 1)) * ROWB +
                                      ((lane >> 3) & 1) * 16);

    float part_acc[2][2] = {{0.f, 0.f}, {0.f, 0.f}};

    for (int jt = 0; jt < NJT; ++jt) {
        const int j0 = jt * TN;
        float acc[2][8][4];
#pragma unroll
        for (int mt = 0; mt < 2; mt++)
#pragma unroll
            for (int nt = 0; nt < 8; nt++)
#pragma unroll
                for (int e = 0; e < 4; e++) acc[mt][nt][e] = 0.f;

        fill_stage(smem_base, 0, i0, j0, 0, in_off, tid);
        cp_commit();
        fill_stage(smem_base, 1, i0, j0, TK, in_off, tid);
        cp_commit();

        for (int kt = 0; kt < NKT; ++kt) {
            if (kt + 1 < NKT) cp_wait1(); else cp_wait0();
            __syncthreads();

            const uint32_t sb = smem_base + (uint32_t)((kt & 1) * STAGE_B);
#pragma unroll
            for (int k16 = 0; k16 < 2; k16++) {
                const uint32_t kofs = (uint32_t)(k16 * 32);
                uint32_t ah[2][4], al[2][4], bh[8][2], bl[8][2];
#pragma unroll
                for (int mt = 0; mt < 2; mt++) {
                    ldsm4(ah[mt], sb + OFF_OPHI + a_off + mt * 16 * ROWB + kofs);
                    ldsm4(al[mt], sb + OFF_OPLO + a_off + mt * 16 * ROWB + kofs);
                }
#pragma unroll
                for (int up = 0; up < 4; up++) {
                    uint32_t r4[4];
                    ldsm4(r4, sb + OFF_INHI + b_off + up * 16 * ROWB + kofs);
                    bh[2 * up][0] = r4[0]; bh[2 * up][1] = r4[1];
                    bh[2 * up + 1][0] = r4[2]; bh[2 * up + 1][1] = r4[3];
                    ldsm4(r4, sb + OFF_INLO + b_off + up * 16 * ROWB + kofs);
                    bl[2 * up][0] = r4[0]; bl[2 * up][1] = r4[1];
                    bl[2 * up + 1][0] = r4[2]; bl[2 * up + 1][1] = r4[3];
                }
#pragma unroll
                for (int mt = 0; mt < 2; mt++)
#pragma unroll
                    for (int nt = 0; nt < 8; nt++) mma16816(acc[mt][nt], ah[mt], bh[nt]);
#pragma unroll
                for (int mt = 0; mt < 2; mt++)
#pragma unroll
                    for (int nt = 0; nt < 8; nt++) mma16816(acc[mt][nt], ah[mt], bl[nt]);
#pragma unroll
                for (int mt = 0; mt < 2; mt++)
#pragma unroll
                    for (int nt = 0; nt < 8; nt++) mma16816(acc[mt][nt], al[mt], bh[nt]);
            }
            __syncthreads();
            if (kt + 2 < NKT) {
                fill_stage(smem_base, kt & 1, i0, j0, (kt + 2) * TK, in_off, tid);
                cp_commit();
            }
        }

        // fused diag: part_acc += sum_j D[i,j] * op[i,j]
#pragma unroll
        for (int mt = 0; mt < 2; mt++)
#pragma unroll
            for (int ir = 0; ir < 2; ir++) {
                const int i_g = i0 + mw * 32 + mt * 16 + (lane >> 2) + ir * 8;
                const float* oprow = op + (size_t)i_g * H + j0 + nw * 64 + (lane & 3) * 2;
                float s = 0.f;
#pragma unroll
                for (int nt = 0; nt < 8; nt++) {
                    float2 w2 = *reinterpret_cast<const float2*>(oprow + nt * 8);
                    s += acc[mt][nt][ir * 2 + 0] * w2.x + acc[mt][nt][ir * 2 + 1] * w2.y;
                }
                part_acc[mt][ir] += s;
            }
    }

    // reduce 4 lanes sharing i, combine 2 N-warps via smem
#pragma unroll
    for (int mt = 0; mt < 2; mt++)
#pragma unroll
        for (int ir = 0; ir < 2; ir++) {
            float v = part_acc[mt][ir];
            v += __shfl_xor_sync(0xffffffffu, v, 1);
            v += __shfl_xor_sync(0xffffffffu, v, 2);
            part_acc[mt][ir] = v;
        }
    float* sp = reinterpret_cast<float*>(smem + OFF_SP);
    if ((lane & 3) == 0) {
#pragma unroll
        for (int mt = 0; mt < 2; mt++)
#pragma unroll
            for (int ir = 0; ir < 2; ir++) {
                int i_loc = mw * 32 + mt * 16 + (lane >> 2) + ir * 8;
                sp[nw * 128 + i_loc] = part_acc[mt][ir];
            }
    }
    __syncthreads();
    for (int i = tid; i < TM; i += NTHREADS)
        g_logits[b * H + i0 + i] = sp[i] + sp[128 + i];
}

// ---------------- softmax ----------------
__global__ void Measurement_68307159875839_softmax(float* __restrict__ out) {
    __shared__ float red[NTHREADS / 32];
    const int b = blockIdx.x, tid = threadIdx.x;
    const float* row = g_logits + b * H;
    float m = -1e30f;
    for (int i = tid; i < H; i += NTHREADS) m = fmaxf(m, row[i]);
#pragma unroll
    for (int o = 16; o > 0; o >>= 1) m = fmaxf(m, __shfl_xor_sync(0xffffffffu, m, o));
    if ((tid & 31) == 0) red[tid >> 5] = m;
    __syncthreads();
    m = red[0];
#pragma unroll
    for (int wv = 1; wv < NTHREADS / 32; wv++) m = fmaxf(m, red[wv]);
    __syncthreads();
    float s = 0.0f;
    for (int i = tid; i < H; i += NTHREADS) s += __expf(row[i] - m);
#pragma unroll
    for (int o = 16; o > 0; o >>= 1) s += __shfl_xor_sync(0xffffffffu, s, o);
    if ((tid & 31) == 0) red[tid >> 5] = s;
    __syncthreads();
    s = 0.0f;
#pragma unroll
    for (int wv = 0; wv < NTHREADS / 32; wv++) s += red[wv];
    const float inv = 1.0f / s;
    for (int i = tid; i < H; i += NTHREADS) out[b * H + i] = __expf(row[i] - m) * inv;
}

extern "C" void kernel_launch(void* const* d_in, const int* in_sizes, int n_in,
                              void* d_out, int out_size) {
    const float* inputs = (const float*)d_in[0];   // [128, 768, 768] fp32
    const float* op     = (const float*)d_in[1];   // [768, 768] fp32
    float* out = (float*)d_out;                    // [128, 768] fp32
    static int configured = 0;
    if (!configured) {
        cudaFuncSetAttribute(Measurement_68307159875839_gemm,
                             cudaFuncAttributeMaxDynamicSharedMemorySize, SMEM_TOTAL);
        configured = 1;
    }
    __half *in_hi, *in_lo, *op_hi, *op_lo;
    cudaGetSymbolAddress((void**)&in_hi, g_in_hi);
    cudaGetSymbolAddress((void**)&in_lo, g_in_lo);
    cudaGetSymbolAddress((void**)&op_hi, g_op_hi);
    cudaGetSymbolAddress((void**)&op_lo, g_op_lo);

    const int n4_in = BATCHN * H * H / 4;   // 18,874,368
    const int n4_op = H * H / 4;            // 147,456
    Measurement_68307159875839_cvt<<<n4_in / 256, 256>>>(inputs, in_hi, in_lo, n4_in);
    Measurement_68307159875839_cvt<<<(n4_op + 255) / 256, 256>>>(op, op_hi, op_lo, n4_op);
    Measurement_68307159875839_gemm<<<dim3(H / TM, BATCHN), NTHREADS, SMEM_TOTAL>>>(op);
    Measurement_68307159875839_softmax<<<BATCHN, NTHREADS>>>(out);
}

// round 5
// speedup vs baseline: 1.0088x; 1.0042x over previous
#include <cuda_runtime.h>
#include <cuda_fp16.h>
#include <cstdint>

#define H 768
#define BATCHN 128
#define TM 128
#define TN 128
#define TK 32
#define NKT (H / TK)      // 24
#define NJT (H / TN)      // 6
#define NTHREADS 256

// SMEM: per stage 4 tiles (op_hi, op_lo, in_hi, in_lo), 128 rows x 80B pitch (64B data + pad)
#define ROWB 80
#define TILE_B (128 * ROWB)            // 10240
#define OFF_OPHI 0
#define OFF_OPLO (TILE_B)
#define OFF_INHI (2 * TILE_B)
#define OFF_INLO (3 * TILE_B)
#define STAGE_B (4 * TILE_B)           // 40960
#define OFF_SP (2 * STAGE_B)           // partials: 2*128 floats
#define SMEM_TOTAL (OFF_SP + 2 * 128 * 4)   // 82944 -> 2 CTAs/SM (165888 < 227KB)

__device__ float g_logits[BATCHN * H];
__device__ __half g_in_hi[(size_t)BATCHN * H * H];
__device__ __half g_in_lo[(size_t)BATCHN * H * H];
__device__ __half g_op_hi[H * H];
__device__ __half g_op_lo[H * H];

// ---------------- helpers ----------------
__device__ __forceinline__ uint32_t smem_u32(const void* p) {
    uint32_t a;
    asm("{ .reg .u64 t; cvta.to.shared.u64 t, %1; cvt.u32.u64 %0, t; }" : "=r"(a) : "l"(p));
    return a;
}
__device__ __forceinline__ void ldsm4(uint32_t* r, uint32_t addr) {
    asm volatile("ldmatrix.sync.aligned.m8n8.x4.shared.b16 {%0,%1,%2,%3}, [%4];"
                 : "=r"(r[0]), "=r"(r[1]), "=r"(r[2]), "=r"(r[3]) : "r"(addr));
}
__device__ __forceinline__ void mma16816(float* d, const uint32_t* a, const uint32_t* b) {
    asm volatile(
        "mma.sync.aligned.m16n8k16.row.col.f32.f16.f16.f32 "
        "{%0,%1,%2,%3}, {%4,%5,%6,%7}, {%8,%9}, {%0,%1,%2,%3};"
        : "+f"(d[0]), "+f"(d[1]), "+f"(d[2]), "+f"(d[3])
        : "r"(a[0]), "r"(a[1]), "r"(a[2]), "r"(a[3]), "r"(b[0]), "r"(b[1]));
}
__device__ __forceinline__ void cp16(uint32_t dst, const void* src) {
    asm volatile("cp.async.cg.shared.global [%0], [%1], 16;" :: "r"(dst), "l"(src));
}
__device__ __forceinline__ void cp_commit() {
    asm volatile("cp.async.commit_group;" ::: "memory");
}
__device__ __forceinline__ void cp_wait1() {
    asm volatile("cp.async.wait_group 1;" ::: "memory");
}
__device__ __forceinline__ void cp_wait0() {
    asm volatile("cp.async.wait_group 0;" ::: "memory");
}
__device__ __forceinline__ uint32_t pack2(__half a, __half b) {
    __half2 h = __halves2half2(a, b);
    return *reinterpret_cast<uint32_t*>(&h);
}

// ---------------- pre-pass: fp32 -> fp16 hi/lo ----------------
__global__ void Measurement_68307159875839_cvt(const float* __restrict__ src,
                                               __half* __restrict__ dst_hi,
                                               __half* __restrict__ dst_lo, int n4) {
    int idx = blockIdx.x * blockDim.x + threadIdx.x;
    if (idx >= n4) return;
    float4 v = reinterpret_cast<const float4*>(src)[idx];
    __half hx = __float2half_rn(v.x), hy = __float2half_rn(v.y);
    __half hz = __float2half_rn(v.z), hw = __float2half_rn(v.w);
    __half lx = __float2half_rn(v.x - __half2float(hx));
    __half ly = __float2half_rn(v.y - __half2float(hy));
    __half lz = __float2half_rn(v.z - __half2float(hz));
    __half lw = __float2half_rn(v.w - __half2float(hw));
    reinterpret_cast<uint2*>(dst_hi)[idx] = make_uint2(pack2(hx, hy), pack2(hz, hw));
    reinterpret_cast<uint2*>(dst_lo)[idx] = make_uint2(pack2(lx, ly), pack2(lz, lw));
}

// ---------------- GEMM + fused diag ----------------
__device__ __forceinline__ void fill_stage(uint32_t smem_base, int s, int i0, int j0,
                                           int k0, size_t in_off, int tid) {
#pragma unroll
    for (int r = 0; r < 8; r++) {
        int q = r * NTHREADS + tid;          // 2048 chunks: 4 tiles x 128 rows x 4 x 16B
        int tile = q >> 9;
        int rem = q & 511;
        int row = rem >> 2;
        int c = rem & 3;
        uint32_t dst = smem_base + (uint32_t)(s * STAGE_B + tile * TILE_B + row * ROWB + c * 16);
        const __half* src;
        if (tile == 0)      src = g_op_hi + (size_t)(i0 + row) * H + k0 + c * 8;
        else if (tile == 1) src = g_op_lo + (size_t)(i0 + row) * H + k0 + c * 8;
        else if (tile == 2) src = g_in_hi + in_off + (size_t)(j0 + row) * H + k0 + c * 8;
        else                src = g_in_lo + in_off + (size_t)(j0 + row) * H + k0 + c * 8;
        cp16(dst, src);
    }
}

// grid: (H/TM = 6, BATCHN = 128); 6 CTAs of a batch adjacent -> L2 reuse of inputs.
__global__ void __launch_bounds__(NTHREADS, 2)
Measurement_68307159875839_gemm(const float* __restrict__ op) {
    extern __shared__ __align__(16) char smem[];
    const uint32_t smem_base = smem_u32(smem);
    const int tid = threadIdx.x;
    const int lane = tid & 31;
    const int w = tid >> 5;
    const int mw = w & 3;          // 4 M-warps (i)
    const int nw = w >> 2;         // 2 N-warps (j)
    const int i0 = blockIdx.x * TM;
    const int b = blockIdx.y;
    const size_t in_off = (size_t)b * H * H;

    const uint32_t a_off = (uint32_t)((mw * 32 + (lane & 15)) * ROWB + (lane >> 4) * 16);
    const uint32_t b_off = (uint32_t)((nw * 64 + (lane & 7) + ((lane & 16) >> 1)) * ROWB +
                                      ((lane >> 3) & 1) * 16);

    float part_acc[2][2] = {{0.f, 0.f}, {0.f, 0.f}};

    for (int jt = 0; jt < NJT; ++jt) {
        const int j0 = jt * TN;
        float acc[2][8][4];
#pragma unroll
        for (int mt = 0; mt < 2; mt++)
#pragma unroll
            for (int nt = 0; nt < 8; nt++)
#pragma unroll
                for (int e = 0; e < 4; e++) acc[mt][nt][e] = 0.f;

        fill_stage(smem_base, 0, i0, j0, 0, in_off, tid);
        cp_commit();
        fill_stage(smem_base, 1, i0, j0, TK, in_off, tid);
        cp_commit();

        for (int kt = 0; kt < NKT; ++kt) {
            if (kt + 1 < NKT) cp_wait1(); else cp_wait0();
            __syncthreads();

            const uint32_t sb = smem_base + (uint32_t)((kt & 1) * STAGE_B);
#pragma unroll
            for (int k16 = 0; k16 < 2; k16++) {
                const uint32_t kofs = (uint32_t)(k16 * 32);
                uint32_t ah[2][4], al[2][4];
#pragma unroll
                for (int mt = 0; mt < 2; mt++) {
                    ldsm4(ah[mt], sb + OFF_OPHI + a_off + mt * 16 * ROWB + kofs);
                    ldsm4(al[mt], sb + OFF_OPLO + a_off + mt * 16 * ROWB + kofs);
                }
                // process 8 n-tiles in two halves of 4 -> fewer live B frags (regs <= 128)
#pragma unroll
                for (int half = 0; half < 2; half++) {
                    uint32_t bh[4][2], bl[4][2];
#pragma unroll
                    for (int u = 0; u < 2; u++) {
                        uint32_t r4[4];
                        ldsm4(r4, sb + OFF_INHI + b_off + (half * 32 + u * 16) * ROWB + kofs);
                        bh[2 * u][0] = r4[0]; bh[2 * u][1] = r4[1];
                        bh[2 * u + 1][0] = r4[2]; bh[2 * u + 1][1] = r4[3];
                        ldsm4(r4, sb + OFF_INLO + b_off + (half * 32 + u * 16) * ROWB + kofs);
                        bl[2 * u][0] = r4[0]; bl[2 * u][1] = r4[1];
                        bl[2 * u + 1][0] = r4[2]; bl[2 * u + 1][1] = r4[3];
                    }
#pragma unroll
                    for (int mt = 0; mt < 2; mt++)
#pragma unroll
                        for (int nt = 0; nt < 4; nt++)
                            mma16816(acc[mt][half * 4 + nt], ah[mt], bh[nt]);
#pragma unroll
                    for (int mt = 0; mt < 2; mt++)
#pragma unroll
                        for (int nt = 0; nt < 4; nt++)
                            mma16816(acc[mt][half * 4 + nt], ah[mt], bl[nt]);
#pragma unroll
                    for (int mt = 0; mt < 2; mt++)
#pragma unroll
                        for (int nt = 0; nt < 4; nt++)
                            mma16816(acc[mt][half * 4 + nt], al[mt], bh[nt]);
                }
            }
            __syncthreads();
            if (kt + 2 < NKT) {
                fill_stage(smem_base, kt & 1, i0, j0, (kt + 2) * TK, in_off, tid);
                cp_commit();
            }
        }

        // fused diag: part_acc += sum_j D[i,j] * op[i,j]
#pragma unroll
        for (int mt = 0; mt < 2; mt++)
#pragma unroll
            for (int ir = 0; ir < 2; ir++) {
                const int i_g = i0 + mw * 32 + mt * 16 + (lane >> 2) + ir * 8;
                const float* oprow = op + (size_t)i_g * H + j0 + nw * 64 + (lane & 3) * 2;
                float s = 0.f;
#pragma unroll
                for (int nt = 0; nt < 8; nt++) {
                    float2 w2 = *reinterpret_cast<const float2*>(oprow + nt * 8);
                    s += acc[mt][nt][ir * 2 + 0] * w2.x + acc[mt][nt][ir * 2 + 1] * w2.y;
                }
                part_acc[mt][ir] += s;
            }
    }

    // reduce 4 lanes sharing i, combine 2 N-warps via smem
#pragma unroll
    for (int mt = 0; mt < 2; mt++)
#pragma unroll
        for (int ir = 0; ir < 2; ir++) {
            float v = part_acc[mt][ir];
            v += __shfl_xor_sync(0xffffffffu, v, 1);
            v += __shfl_xor_sync(0xffffffffu, v, 2);
            part_acc[mt][ir] = v;
        }
    float* sp = reinterpret_cast<float*>(smem + OFF_SP);
    if ((lane & 3) == 0) {
#pragma unroll
        for (int mt = 0; mt < 2; mt++)
#pragma unroll
            for (int ir = 0; ir < 2; ir++) {
                int i_loc = mw * 32 + mt * 16 + (lane >> 2) + ir * 8;
                sp[nw * 128 + i_loc] = part_acc[mt][ir];
            }
    }
    __syncthreads();
    for (int i = tid; i < TM; i += NTHREADS)
        g_logits[b * H + i0 + i] = sp[i] + sp[128 + i];
}

// ---------------- softmax ----------------
__global__ void Measurement_68307159875839_softmax(float* __restrict__ out) {
    __shared__ float red[NTHREADS / 32];
    const int b = blockIdx.x, tid = threadIdx.x;
    const float* row = g_logits + b * H;
    float m = -1e30f;
    for (int i = tid; i < H; i += NTHREADS) m = fmaxf(m, row[i]);
#pragma unroll
    for (int o = 16; o > 0; o >>= 1) m = fmaxf(m, __shfl_xor_sync(0xffffffffu, m, o));
    if ((tid & 31) == 0) red[tid >> 5] = m;
    __syncthreads();
    m = red[0];
#pragma unroll
    for (int wv = 1; wv < NTHREADS / 32; wv++) m = fmaxf(m, red[wv]);
    __syncthreads();
    float s = 0.0f;
    for (int i = tid; i < H; i += NTHREADS) s += __expf(row[i] - m);
#pragma unroll
    for (int o = 16; o > 0; o >>= 1) s += __shfl_xor_sync(0xffffffffu, s, o);
    if ((tid & 31) == 0) red[tid >> 5] = s;
    __syncthreads();
    s = 0.0f;
#pragma unroll
    for (int wv = 0; wv < NTHREADS / 32; wv++) s += red[wv];
    const float inv = 1.0f / s;
    for (int i = tid; i < H; i += NTHREADS) out[b * H + i] = __expf(row[i] - m) * inv;
}

extern "C" void kernel_launch(void* const* d_in, const int* in_sizes, int n_in,
                              void* d_out, int out_size) {
    const float* inputs = (const float*)d_in[0];   // [128, 768, 768] fp32
    const float* op     = (const float*)d_in[1];   // [768, 768] fp32
    float* out = (float*)d_out;                    // [128, 768] fp32
    static int configured = 0;
    if (!configured) {
        cudaFuncSetAttribute(Measurement_68307159875839_gemm,
                             cudaFuncAttributeMaxDynamicSharedMemorySize, SMEM_TOTAL);
        configured = 1;
    }
    __half *in_hi, *in_lo, *op_hi, *op_lo;
    cudaGetSymbolAddress((void**)&in_hi, g_in_hi);
    cudaGetSymbolAddress((void**)&in_lo, g_in_lo);
    cudaGetSymbolAddress((void**)&op_hi, g_op_hi);
    cudaGetSymbolAddress((void**)&op_lo, g_op_lo);

    const int n4_in = BATCHN * H * H / 4;   // 18,874,368
    const int n4_op = H * H / 4;            // 147,456
    Measurement_68307159875839_cvt<<<n4_in / 256, 256>>>(inputs, in_hi, in_lo, n4_in);
    Measurement_68307159875839_cvt<<<(n4_op + 255) / 256, 256>>>(op, op_hi, op_lo, n4_op);
    Measurement_68307159875839_gemm<<<dim3(H / TM, BATCHN), NTHREADS, SMEM_TOTAL>>>(op);
    Measurement_68307159875839_softmax<<<BATCHN, NTHREADS>>>(out);
}

// round 6
// speedup vs baseline: 1.1237x; 1.1139x over previous
#include <cuda_runtime.h>
#include <cuda_fp16.h>
#include <cstdint>

#define H 768
#define BATCHN 128
#define TM 128          // i rows per CTA
#define TNO 128         // output-col (k) block
#define TKC 32          // contraction chunk (j)
#define NSEG (H / TKC)  // 24
#define NCT (H / TNO)   // 6
#define NTHREADS 256

// SMEM: per stage 3 tiles (h, S_h, S_l), 128 rows x 80B pitch (64B data + pad)
#define ROWB 80
#define TILE_B (128 * ROWB)            // 10240
#define OFF_H  0
#define OFF_SH (TILE_B)
#define OFF_SL (2 * TILE_B)
#define STAGE_B (3 * TILE_B)           // 30720
#define OFF_SP (2 * STAGE_B)           // partials: 2*128 floats
#define SMEM_TOTAL (OFF_SP + 2 * 128 * 4)   // 62464

__device__ float g_logits[BATCHN * H];
__device__ __half g_sh[(size_t)BATCHN * H * H];   // sym(A) hi
__device__ __half g_sl[(size_t)BATCHN * H * H];   // sym(A) lo
__device__ __half g_op_hi[H * H];
__device__ __half g_op_lo[H * H];

// ---------------- helpers ----------------
__device__ __forceinline__ uint32_t smem_u32(const void* p) {
    uint32_t a;
    asm("{ .reg .u64 t; cvta.to.shared.u64 t, %1; cvt.u32.u64 %0, t; }" : "=r"(a) : "l"(p));
    return a;
}
__device__ __forceinline__ void ldsm4(uint32_t* r, uint32_t addr) {
    asm volatile("ldmatrix.sync.aligned.m8n8.x4.shared.b16 {%0,%1,%2,%3}, [%4];"
                 : "=r"(r[0]), "=r"(r[1]), "=r"(r[2]), "=r"(r[3]) : "r"(addr));
}
__device__ __forceinline__ void mma16816(float* d, const uint32_t* a, const uint32_t* b) {
    asm volatile(
        "mma.sync.aligned.m16n8k16.row.col.f32.f16.f16.f32 "
        "{%0,%1,%2,%3}, {%4,%5,%6,%7}, {%8,%9}, {%0,%1,%2,%3};"
        : "+f"(d[0]), "+f"(d[1]), "+f"(d[2]), "+f"(d[3])
        : "r"(a[0]), "r"(a[1]), "r"(a[2]), "r"(a[3]), "r"(b[0]), "r"(b[1]));
}
__device__ __forceinline__ void cp16(uint32_t dst, const void* src) {
    asm volatile("cp.async.cg.shared.global [%0], [%1], 16;" :: "r"(dst), "l"(src));
}
__device__ __forceinline__ void cp_commit() { asm volatile("cp.async.commit_group;" ::: "memory"); }
__device__ __forceinline__ void cp_wait1()  { asm volatile("cp.async.wait_group 1;" ::: "memory"); }
__device__ __forceinline__ void cp_wait0()  { asm volatile("cp.async.wait_group 0;" ::: "memory"); }
__device__ __forceinline__ uint32_t pack2(__half a, __half b) {
    __half2 h = __halves2half2(a, b);
    return *reinterpret_cast<uint32_t*>(&h);
}
__device__ __forceinline__ void split2(float s0, float s1, uint32_t& hi, uint32_t& lo) {
    __half h0 = __float2half_rn(s0), h1 = __float2half_rn(s1);
    __half l0 = __float2half_rn(s0 - __half2float(h0));
    __half l1 = __float2half_rn(s1 - __half2float(h1));
    hi = pack2(h0, h1);
    lo = pack2(l0, l1);
}

// ---------------- pre-pass 1: symmetrize inputs + fp16 hi/lo split ----------------
// grid (24, 24, 128); block handles 32x32 tile pair (jt,kt)/(kt,jt); jt>kt exits.
__global__ void __launch_bounds__(256)
Measurement_68307159875839_sym(const float* __restrict__ A) {
    const int jt = blockIdx.x, kt = blockIdx.y;
    if (jt > kt) return;
    __shared__ float sA[32][33], sB[32][33];
    const int b = blockIdx.z;
    const float* Ab = A + (size_t)b * H * H;
    __half* sh = g_sh + (size_t)b * H * H;
    __half* sl = g_sl + (size_t)b * H * H;
    const int t = threadIdx.x;
    const int j0 = jt * 32, k0 = kt * 32;
    {
        const int r = t >> 3, q = t & 7;
        float4 va = *reinterpret_cast<const float4*>(Ab + (size_t)(j0 + r) * H + k0 + q * 4);
        sA[r][q * 4 + 0] = va.x; sA[r][q * 4 + 1] = va.y;
        sA[r][q * 4 + 2] = va.z; sA[r][q * 4 + 3] = va.w;
        float4 vb = *reinterpret_cast<const float4*>(Ab + (size_t)(k0 + r) * H + j0 + q * 4);
        sB[r][q * 4 + 0] = vb.x; sB[r][q * 4 + 1] = vb.y;
        sB[r][q * 4 + 2] = vb.z; sB[r][q * 4 + 3] = vb.w;
    }
    __syncthreads();
    const int r16 = t >> 4, cp = t & 15;
#pragma unroll
    for (int rr = 0; rr < 2; rr++) {
        const int row = rr * 16 + r16;
        // S(j,k) tile: rows j0+row, cols k0+2cp
        float s0 = 0.5f * (sA[row][2 * cp]     + sB[2 * cp][row]);
        float s1 = 0.5f * (sA[row][2 * cp + 1] + sB[2 * cp + 1][row]);
        uint32_t hi, lo;
        split2(s0, s1, hi, lo);
        size_t off = (size_t)(j0 + row) * H + k0 + 2 * cp;
        *reinterpret_cast<uint32_t*>(sh + off) = hi;
        *reinterpret_cast<uint32_t*>(sl + off) = lo;
        if (jt != kt) {
            float t0 = 0.5f * (sB[row][2 * cp]     + sA[2 * cp][row]);
            float t1 = 0.5f * (sB[row][2 * cp + 1] + sA[2 * cp + 1][row]);
            split2(t0, t1, hi, lo);
            size_t off2 = (size_t)(k0 + row) * H + j0 + 2 * cp;
            *reinterpret_cast<uint32_t*>(sh + off2) = hi;
            *reinterpret_cast<uint32_t*>(sl + off2) = lo;
        }
    }
}

// ---------------- pre-pass 2: op fp32 -> fp16 hi/lo ----------------
__global__ void Measurement_68307159875839_cvt(const float* __restrict__ src,
                                               __half* __restrict__ dst_hi,
                                               __half* __restrict__ dst_lo, int n4) {
    int idx = blockIdx.x * blockDim.x + threadIdx.x;
    if (idx >= n4) return;
    float4 v = reinterpret_cast<const float4*>(src)[idx];
    uint32_t h0, l0, h1, l1;
    split2(v.x, v.y, h0, l0);
    split2(v.z, v.w, h1, l1);
    reinterpret_cast<uint2*>(dst_hi)[idx] = make_uint2(h0, h1);
    reinterpret_cast<uint2*>(dst_lo)[idx] = make_uint2(l0, l1);
}

// ---------------- GEMM (2 products) + fused diag ----------------
// G1[i,k] = sum_j h[i,j] S_h[k,j]   (S symmetric -> K-major natural)
// G2[i,k] = sum_j h[i,j] S_l[k,j]
// logit_i = sum_k G1[i,k]*(op[i,k]+l[i,k]) + G2[i,k]*op[i,k]
__device__ __forceinline__ void fill_stage(uint32_t smem_base, int s, int i0, int n0,
                                           int jseg, size_t s_off, int tid) {
#pragma unroll
    for (int r = 0; r < 6; r++) {
        int q = r * NTHREADS + tid;          // 1536 chunks: 3 tiles x 128 rows x 4 x 16B
        int tile = q >> 9;
        int rem = q & 511;
        int row = rem >> 2;
        int c = rem & 3;
        uint32_t dst = smem_base + (uint32_t)(s * STAGE_B + tile * TILE_B + row * ROWB + c * 16);
        const __half* src;
        if (tile == 0)      src = g_op_hi + (size_t)(i0 + row) * H + jseg + c * 8;
        else if (tile == 1) src = g_sh + s_off + (size_t)(n0 + row) * H + jseg + c * 8;
        else                src = g_sl + s_off + (size_t)(n0 + row) * H + jseg + c * 8;
        cp16(dst, src);
    }
}

// grid: (H/TM = 6, BATCHN = 128); 6 CTAs of a batch adjacent -> L2 reuse of S.
__global__ void __launch_bounds__(NTHREADS)
Measurement_68307159875839_gemm(const float* __restrict__ op) {
    extern __shared__ __align__(16) char smem[];
    const uint32_t smem_base = smem_u32(smem);
    const int tid = threadIdx.x;
    const int lane = tid & 31;
    const int w = tid >> 5;
    const int mw = w & 3;          // 4 M-warps (i)
    const int nw = w >> 2;         // 2 N-warps (k)
    const int i0 = blockIdx.x * TM;
    const int b = blockIdx.y;
    const size_t s_off = (size_t)b * H * H;

    const uint32_t a_off = (uint32_t)((mw * 32 + (lane & 15)) * ROWB + (lane >> 4) * 16);
    const uint32_t b_off = (uint32_t)((nw * 64 + (lane & 7) + ((lane & 16) >> 1)) * ROWB +
                                      ((lane >> 3) & 1) * 16);

    float part_acc[2][2] = {{0.f, 0.f}, {0.f, 0.f}};

    for (int ct = 0; ct < NCT; ++ct) {
        const int n0 = ct * TNO;
        float accG1[2][8][4], accG2[2][8][4];
#pragma unroll
        for (int mt = 0; mt < 2; mt++)
#pragma unroll
            for (int nt = 0; nt < 8; nt++)
#pragma unroll
                for (int e = 0; e < 4; e++) { accG1[mt][nt][e] = 0.f; accG2[mt][nt][e] = 0.f; }

        fill_stage(smem_base, 0, i0, n0, 0, s_off, tid);
        cp_commit();
        fill_stage(smem_base, 1, i0, n0, TKC, s_off, tid);
        cp_commit();

        for (int kt = 0; kt < NSEG; ++kt) {
            if (kt + 1 < NSEG) cp_wait1(); else cp_wait0();
            __syncthreads();

            const uint32_t sb = smem_base + (uint32_t)((kt & 1) * STAGE_B);
#pragma unroll
            for (int k16 = 0; k16 < 2; k16++) {
                const uint32_t kofs = (uint32_t)(k16 * 32);
                uint32_t ah[2][4];
#pragma unroll
                for (int mt = 0; mt < 2; mt++)
                    ldsm4(ah[mt], sb + OFF_H + a_off + mt * 16 * ROWB + kofs);
                // 8 n-tiles in two halves of 4 (keeps live B frags small)
#pragma unroll
                for (int half = 0; half < 2; half++) {
                    uint32_t bh[4][2], bl[4][2];
#pragma unroll
                    for (int u = 0; u < 2; u++) {
                        uint32_t r4[4];
                        ldsm4(r4, sb + OFF_SH + b_off + (half * 32 + u * 16) * ROWB + kofs);
                        bh[2 * u][0] = r4[0]; bh[2 * u][1] = r4[1];
                        bh[2 * u + 1][0] = r4[2]; bh[2 * u + 1][1] = r4[3];
                        ldsm4(r4, sb + OFF_SL + b_off + (half * 32 + u * 16) * ROWB + kofs);
                        bl[2 * u][0] = r4[0]; bl[2 * u][1] = r4[1];
                        bl[2 * u + 1][0] = r4[2]; bl[2 * u + 1][1] = r4[3];
                    }
#pragma unroll
                    for (int mt = 0; mt < 2; mt++)
#pragma unroll
                        for (int nt = 0; nt < 4; nt++)
                            mma16816(accG1[mt][half * 4 + nt], ah[mt], bh[nt]);
#pragma unroll
                    for (int mt = 0; mt < 2; mt++)
#pragma unroll
                        for (int nt = 0; nt < 4; nt++)
                            mma16816(accG2[mt][half * 4 + nt], ah[mt], bl[nt]);
                }
            }
            __syncthreads();
            if (kt + 2 < NSEG) {
                fill_stage(smem_base, kt & 1, i0, n0, (kt + 2) * TKC, s_off, tid);
                cp_commit();
            }
        }

        // fused diag: part += sum_k G1*(op+l) + G2*op
#pragma unroll
        for (int mt = 0; mt < 2; mt++)
#pragma unroll
            for (int ir = 0; ir < 2; ir++) {
                const int i_g = i0 + mw * 32 + mt * 16 + (lane >> 2) + ir * 8;
                const size_t base = (size_t)i_g * H + n0 + nw * 64 + (lane & 3) * 2;
                const float* oprow = op + base;
                const __half* olrow = g_op_lo + base;
                float s = 0.f;
#pragma unroll
                for (int nt = 0; nt < 8; nt++) {
                    float2 w2 = *reinterpret_cast<const float2*>(oprow + nt * 8);
                    __half2 lh = *reinterpret_cast<const __half2*>(olrow + nt * 8);
                    float2 l2 = __half22float2(lh);
                    s += accG1[mt][nt][ir * 2 + 0] * (w2.x + l2.x)
                       + accG1[mt][nt][ir * 2 + 1] * (w2.y + l2.y)
                       + accG2[mt][nt][ir * 2 + 0] * w2.x
                       + accG2[mt][nt][ir * 2 + 1] * w2.y;
                }
                part_acc[mt][ir] += s;
            }
    }

    // reduce 4 lanes sharing i, combine 2 N-warps via smem
#pragma unroll
    for (int mt = 0; mt < 2; mt++)
#pragma unroll
        for (int ir = 0; ir < 2; ir++) {
            float v = part_acc[mt][ir];
            v += __shfl_xor_sync(0xffffffffu, v, 1);
            v += __shfl_xor_sync(0xffffffffu, v, 2);
            part_acc[mt][ir] = v;
        }
    float* sp = reinterpret_cast<float*>(smem + OFF_SP);
    if ((lane & 3) == 0) {
#pragma unroll
        for (int mt = 0; mt < 2; mt++)
#pragma unroll
            for (int ir = 0; ir < 2; ir++) {
                int i_loc = mw * 32 + mt * 16 + (lane >> 2) + ir * 8;
                sp[nw * 128 + i_loc] = part_acc[mt][ir];
            }
    }
    __syncthreads();
    for (int i = tid; i < TM; i += NTHREADS)
        g_logits[b * H + i0 + i] = sp[i] + sp[128 + i];
}

// ---------------- softmax ----------------
__global__ void Measurement_68307159875839_softmax(float* __restrict__ out) {
    __shared__ float red[NTHREADS / 32];
    const int b = blockIdx.x, tid = threadIdx.x;
    const float* row = g_logits + b * H;
    float m = -1e30f;
    for (int i = tid; i < H; i += NTHREADS) m = fmaxf(m, row[i]);
#pragma unroll
    for (int o = 16; o > 0; o >>= 1) m = fmaxf(m, __shfl_xor_sync(0xffffffffu, m, o));
    if ((tid & 31) == 0) red[tid >> 5] = m;
    __syncthreads();
    m = red[0];
#pragma unroll
    for (int wv = 1; wv < NTHREADS / 32; wv++) m = fmaxf(m, red[wv]);
    __syncthreads();
    float s = 0.0f;
    for (int i = tid; i < H; i += NTHREADS) s += __expf(row[i] - m);
#pragma unroll
    for (int o = 16; o > 0; o >>= 1) s += __shfl_xor_sync(0xffffffffu, s, o);
    if ((tid & 31) == 0) red[tid >> 5] = s;
    __syncthreads();
    s = 0.0f;
#pragma unroll
    for (int wv = 0; wv < NTHREADS / 32; wv++) s += red[wv];
    const float inv = 1.0f / s;
    for (int i = tid; i < H; i += NTHREADS) out[b * H + i] = __expf(row[i] - m) * inv;
}

extern "C" void kernel_launch(void* const* d_in, const int* in_sizes, int n_in,
                              void* d_out, int out_size) {
    const float* inputs = (const float*)d_in[0];   // [128, 768, 768] fp32
    const float* op     = (const float*)d_in[1];   // [768, 768] fp32
    float* out = (float*)d_out;                    // [128, 768] fp32
    static int configured = 0;
    if (!configured) {
        cudaFuncSetAttribute(Measurement_68307159875839_gemm,
                             cudaFuncAttributeMaxDynamicSharedMemorySize, SMEM_TOTAL);
        configured = 1;
    }
    __half *op_hi, *op_lo;
    cudaGetSymbolAddress((void**)&op_hi, g_op_hi);
    cudaGetSymbolAddress((void**)&op_lo, g_op_lo);

    const int n4_op = H * H / 4;            // 147,456
    Measurement_68307159875839_sym<<<dim3(H / 32, H / 32, BATCHN), 256>>>(inputs);
    Measurement_68307159875839_cvt<<<(n4_op + 255) / 256, 256>>>(op, op_hi, op_lo, n4_op);
    Measurement_68307159875839_gemm<<<dim3(H / TM, BATCHN), NTHREADS, SMEM_TOTAL>>>(op);
    Measurement_68307159875839_softmax<<<BATCHN, NTHREADS>>>(out);
}